// round 16
// baseline (speedup 1.0000x reference)
#include <cuda_runtime.h>
#include <cuda_bf16.h>

// Problem constants (fixed by the dataset reference)
#define Bq   64
#define Sq   131072
#define SqV  (Sq / 4)
#define WIN  100

#define CHUNK 4096
#define HALO  128                 // halo elements each side (multiple of 32)
#define EXT   (CHUNK + 2*HALO)    // 4608
#define TPB   128
#define NWARP (TPB / 32)
#define CPR   (Sq / CHUNK)        // 32 chunks per row
#define NBLK  (Bq * CPR)          // 2048 blocks, 16 CTAs/SM -> grid resident
#define GRP   (CHUNK / 4 / TPB)   // 8 iterations of 4 elements per thread

#define EXTW  (EXT / 32)          // 144 bitmap words
#define GUARD 4                   // zero guard words each side (formula reads k+-4)
#define PADW  (EXTW + 2*GUARD)    // 152

// Per-(row,chunk) partials: x=sum_masked, y=sum_all, z=count_masked, w=has_pos.
__device__ float4       g_part[NBLK];
__device__ unsigned int g_done;   // zero at start; last block resets -> replay safe

__device__ __forceinline__ float fex2(float x) {
    float r; asm("ex2.approx.ftz.f32 %0, %1;" : "=f"(r) : "f"(x)); return r;
}
__device__ __forceinline__ float flg2(float x) {
    float r; asm("lg2.approx.ftz.f32 %0, %1;" : "=f"(r) : "f"(x)); return r;
}
__device__ __forceinline__ float frcp(float x) {
    float r; asm("rcp.approx.ftz.f32 %0, %1;" : "=f"(r) : "f"(x)); return r;
}

// One element: x0..x2 logits, t class, m mask bit (0/1). aw pre-scaled by ln2.
__device__ __forceinline__ void elem(float x0, float x1, float x2,
                                     int t, unsigned m,
                                     float a0, float a1, float a2,
                                     float& sa, float& sm)
{
    const float L2E = 1.44269504088896340736f;
    float xt  = (t == 0) ? x0 : ((t == 1) ? x1 : x2);
    float xa  = (t == 0) ? x1 : x0;
    float xb  = (t <  2) ? x2 : x1;
    float aw  = (t == 0) ? a0 : ((t == 1) ? a1 : a2);
    float nxt = -xt * L2E;
    float ea  = fex2(__fmaf_rn(xa, L2E, nxt));
    float eb  = fex2(__fmaf_rn(xb, L2E, nxt));
    float q   = 1.f + ea + eb;            // = softmax_sum / e_t
    float ce2 = flg2(q);                  // ln2 folded into aw
    float p   = frcp(q);                  // p_t
    float omp = 1.f - p;
    float f   = aw * (omp * omp) * ce2;
    sa += f;
    if (m) sm += f;
}

__global__ __launch_bounds__(TPB, 16)  // 32 regs, 16 CTAs/SM -> grid resident
void focal_main(const float* __restrict__ inputs,
                const int*   __restrict__ targets,
                const float* __restrict__ alpha,
                float*       __restrict__ out)
{
    __shared__ unsigned sPos[PADW];        // positive-flag bitmap (+guards)
    __shared__ unsigned sMsk[PADW];        // window-mask bitmap
    __shared__ unsigned sClsW[CHUNK / 4];  // packed class bytes (chunk interior)
    __shared__ float rA[NWARP], rB[NWARP], rC[NWARP];
    __shared__ int   rH[NWARP];
    __shared__ float sRS[Bq], sRC[Bq];
    __shared__ bool  sLast;

    const int row        = blockIdx.y;
    const int chunk      = blockIdx.x;
    const int chunkStart = chunk * CHUNK;
    const int tid        = threadIdx.x;
    const int lane       = tid & 31, warp = tid >> 5;

    // ---- Zero bitmap guards.
    if (tid < GUARD) { sPos[tid] = 0; sPos[PADW - 1 - tid] = 0; }

    // ---- Vectorized target load: int4 -> flag nibble -> word via 3x shfl_xor.
    const int4* tgt4     = reinterpret_cast<const int4*>(targets);
    const int   rowVecLo = row * SqV;
    const int   baseVec  = rowVecLo + (chunkStart - HALO) / 4;

    #pragma unroll 1
    for (int it = 0; it < 9; it++) {                 // 9*128 = 1152 vectors exact
        const int vecIdx = it * TPB + tid;
        const int gv     = baseVec + vecIdx;
        const int gvc    = min(max(gv, rowVecLo), rowVecLo + SqV - 1);
        int4 v = __ldg(tgt4 + gvc);
        const bool valid = (unsigned)(gv - rowVecLo) < (unsigned)SqV;

        unsigned nib = (v.x > 0 ? 1u : 0u) | (v.y > 0 ? 2u : 0u)
                     | (v.z > 0 ? 4u : 0u) | (v.w > 0 ? 8u : 0u);
        if (!valid) nib = 0;

        unsigned wv = nib << ((lane & 7) * 4);       // 8 lanes build one word
        wv |= __shfl_xor_sync(0xffffffffu, wv, 1);
        wv |= __shfl_xor_sync(0xffffffffu, wv, 2);
        wv |= __shfl_xor_sync(0xffffffffu, wv, 4);
        if ((lane & 7) == 0) sPos[GUARD + (vecIdx >> 3)] = wv;

        const unsigned ci = (unsigned)(vecIdx - HALO / 4);
        if (ci < (unsigned)(CHUNK / 4))
            sClsW[ci] = (unsigned)(v.x & 3) | ((unsigned)(v.y & 3) << 8)
                      | ((unsigned)(v.z & 3) << 16) | ((unsigned)(v.w & 3) << 24);
    }
    __syncthreads();

    // ---- Closed-form +-100 window mask per word (WIN=100 > 3*32).
    int cm0 = 0, hp0 = 0;
    {
        const unsigned* P = sPos + GUARD;
        #pragma unroll 1
        for (int k = tid; k < EXTW; k += TPB) {
            unsigned any5 = P[k-2] | P[k-1] | P[k] | P[k+1] | P[k+2];
            unsigned F    = any5 ? 0xffffffffu : 0u;

            unsigned u3 = P[k+3];                    // covers bits i >= b-4
            u3 |= u3 << 1;  u3 |= u3 << 2;  u3 |= u3 << 4;
            u3 |= u3 << 8;  u3 |= u3 << 16; u3 |= u3 >> 4;

            unsigned d3 = P[k-3];                    // covers bits i <= b+4
            d3 |= d3 >> 1;  d3 |= d3 >> 2;  d3 |= d3 >> 4;
            d3 |= d3 >> 8;  d3 |= d3 >> 16; d3 |= d3 << 4;

            unsigned n4 = P[k+4] & 0xFu;             // covers bits i >= b+28
            n4 |= n4 << 1; n4 |= n4 << 2;
            unsigned r4 = n4 << 28;

            unsigned h4 = P[k-4] >> 28;              // covers bits i <= b-28
            h4 |= h4 >> 1; h4 |= h4 >> 2;

            unsigned M = F | u3 | d3 | r4 | h4;
            sMsk[GUARD + k] = M;
            if ((unsigned)(k - HALO / 32) < (unsigned)(CHUNK / 32)) {
                cm0 += __popc(M);
                hp0 |= (P[k] != 0u);
            }
        }
    }
    __syncthreads();
    const unsigned* MW = sMsk + GUARD + HALO / 32;

    // ---- Main compute: 4 elements/group, 3x LDG.128, spill-free (champion R11).
    const float LN2 = 0.69314718055994531f;
    const float a0 = __ldg(alpha + 0) * LN2, a1 = __ldg(alpha + 1) * LN2,
                a2 = __ldg(alpha + 2) * LN2;
    const float4* in4 = reinterpret_cast<const float4*>(
        inputs + ((size_t)row * Sq + (size_t)chunkStart) * 3);

    float sm = 0.f, sa = 0.f;

    const int      mShift = (tid & 7) * 4;           // invariant: TPB % 8 == 0
    int            mIdx   = tid >> 3;                // MW word index, step 16/iter
    int            g      = tid;                     // group index, step 128/iter
    const float4*  ptr    = in4 + 3 * tid;           // load pointer, step 384/iter

    #pragma unroll 1
    for (int k = 0; k < GRP; k++) {
        const unsigned tv = sClsW[g];
        const unsigned mk = MW[mIdx] >> mShift;
        float4 A = __ldcs(ptr + 0);
        float4 B = __ldcs(ptr + 1);
        float4 C = __ldcs(ptr + 2);

        elem(A.x, A.y, A.z, (int)( tv        & 3u), mk        & 1u, a0, a1, a2, sa, sm);
        elem(A.w, B.x, B.y, (int)((tv >>  8) & 3u), (mk >> 1) & 1u, a0, a1, a2, sa, sm);
        elem(B.z, B.w, C.x, (int)((tv >> 16) & 3u), (mk >> 2) & 1u, a0, a1, a2, sa, sm);
        elem(C.y, C.z, C.w, (int)((tv >> 24) & 3u), (mk >> 3) & 1u, a0, a1, a2, sa, sm);

        g    += TPB;
        mIdx += TPB / 8;
        ptr  += 3 * TPB;
    }

    // ---- Deterministic block reduction, one float4 store per block.
    int cm = cm0, hp = hp0;
    #pragma unroll
    for (int o = 16; o > 0; o >>= 1) {
        sm += __shfl_down_sync(0xffffffffu, sm, o);
        sa += __shfl_down_sync(0xffffffffu, sa, o);
        cm += __shfl_down_sync(0xffffffffu, cm, o);
        hp |= __shfl_down_sync(0xffffffffu, hp, o);
    }
    if (lane == 0) { rA[warp] = sm; rB[warp] = sa; rC[warp] = (float)cm; rH[warp] = hp; }
    __syncthreads();
    if (tid == 0) {
        float Am = 0.f, Bs = 0.f, Cc = 0.f; int H = 0;
        #pragma unroll
        for (int w = 0; w < NWARP; w++) { Am += rA[w]; Bs += rB[w]; Cc += rC[w]; H |= rH[w]; }
        g_part[row * CPR + chunk] = make_float4(Am, Bs, Cc, (float)H);
        __threadfence();
        unsigned old = atomicAdd(&g_done, 1u);
        sLast = (old == NBLK - 1);
    }
    __syncthreads();

    // ---- Last block finalizes (result independent of which block runs this).
    if (sLast) {
        __threadfence();
        if (tid < Bq) {
            float psm = 0.f, psa = 0.f, pcm = 0.f; int php = 0;
            #pragma unroll 4
            for (int k = 0; k < CPR; k++) {
                float4 p = __ldcg(&g_part[tid * CPR + k]);
                psm += p.x; psa += p.y; pcm += p.z; php |= (p.w != 0.f);
            }
            sRS[tid] = php ? psm : psa;
            sRC[tid] = php ? pcm : (float)Sq;
        }
        __syncthreads();
        if (tid == 0) {
            float ts = 0.f, tc = 0.f;
            #pragma unroll
            for (int i = 0; i < Bq; i++) { ts += sRS[i]; tc += sRC[i]; }
            out[0] = ts / tc;
            g_done = 0;   // reset for next graph replay
        }
    }
}

extern "C" void kernel_launch(void* const* d_in, const int* in_sizes, int n_in,
                              void* d_out, int out_size)
{
    const float* inputs  = (const float*)d_in[0];
    const int*   targets = (const int*)d_in[1];
    const float* alpha   = (const float*)d_in[2];

    dim3 grid(CPR, Bq);
    focal_main<<<grid, TPB>>>(inputs, targets, alpha, (float*)d_out);
}

// round 17
// speedup vs baseline: 1.4152x; 1.4152x over previous
#include <cuda_runtime.h>
#include <cuda_bf16.h>

// Problem constants (fixed by the dataset reference)
#define Bq   64
#define Sq   131072
#define SqV  (Sq / 4)
#define WIN  100

#define CHUNK 4096
#define HALO  128                 // halo elements each side (multiple of 32)
#define EXT   (CHUNK + 2*HALO)    // 4608
#define TPB   128
#define NWARP (TPB / 32)
#define CPR   (Sq / CHUNK)        // 32 chunks per row
#define NBLK  (Bq * CPR)          // 2048 blocks, 16 CTAs/SM -> grid resident
#define GRP   (CHUNK / 4 / TPB)   // 8 vector-groups of 4 elements per thread

#define EXTW  (EXT / 32)          // 144 bitmap words
#define EXTV  (EXT / 4)           // 1152 int4 target vectors
#define GUARD 4                   // zero guard words each side (formula reads k+-4)
#define PADW  (EXTW + 2*GUARD)    // 152

// Per-(row,chunk) partials: x=sum_masked, y=sum_all, z=count_masked, w=has_pos.
__device__ float4       g_part[NBLK];
__device__ unsigned int g_done;   // zero at start; last block resets -> replay safe

__device__ __forceinline__ float fex2(float x) {
    float r; asm("ex2.approx.ftz.f32 %0, %1;" : "=f"(r) : "f"(x)); return r;
}
__device__ __forceinline__ float flg2(float x) {
    float r; asm("lg2.approx.ftz.f32 %0, %1;" : "=f"(r) : "f"(x)); return r;
}
__device__ __forceinline__ float frcp(float x) {
    float r; asm("rcp.approx.ftz.f32 %0, %1;" : "=f"(r) : "f"(x)); return r;
}

// One element: x0..x2 logits, t class, m mask bit (0/1). aw pre-scaled by ln2.
__device__ __forceinline__ void elem(float x0, float x1, float x2,
                                     int t, unsigned m,
                                     float a0, float a1, float a2,
                                     float& sa, float& sm)
{
    const float L2E = 1.44269504088896340736f;
    float xt  = (t == 0) ? x0 : ((t == 1) ? x1 : x2);
    float xa  = (t == 0) ? x1 : x0;
    float xb  = (t <  2) ? x2 : x1;
    float aw  = (t == 0) ? a0 : ((t == 1) ? a1 : a2);
    float nxt = -xt * L2E;
    float ea  = fex2(__fmaf_rn(xa, L2E, nxt));
    float eb  = fex2(__fmaf_rn(xb, L2E, nxt));
    float q   = 1.f + ea + eb;            // = softmax_sum / e_t
    float ce2 = flg2(q);                  // ln2 folded into aw
    float p   = frcp(q);                  // p_t
    float omp = 1.f - p;
    float f   = aw * (omp * omp) * ce2;
    sa += f;
    if (m) sm += f;
}

__global__ __launch_bounds__(TPB, 16)  // 32 regs -> 16 CTAs/SM -> whole grid resident
void focal_main(const float* __restrict__ inputs,
                const int*   __restrict__ targets,
                const float* __restrict__ alpha,
                float*       __restrict__ out)
{
    __shared__ unsigned sPos[PADW];        // positive-flag bitmap (+guards)
    __shared__ unsigned sMsk[PADW];        // window-mask bitmap
    __shared__ unsigned sClsW[CHUNK / 4];  // packed class bytes (chunk interior)
    __shared__ float rA[NWARP], rB[NWARP], rC[NWARP];
    __shared__ int   rH[NWARP];
    __shared__ float sRS[Bq], sRC[Bq];
    __shared__ bool  sLast;

    const int row        = blockIdx.y;
    const int chunk      = blockIdx.x;
    const int chunkStart = chunk * CHUNK;
    const int tid        = threadIdx.x;
    const int lane       = tid & 31, warp = tid >> 5;

    // ---- Zero bitmap guards.
    if (tid < GUARD) { sPos[tid] = 0; sPos[PADW - 1 - tid] = 0; }

    // ---- Vectorized target load: int4 -> flag nibble -> word via 3x shfl_xor.
    const int4* tgt4     = reinterpret_cast<const int4*>(targets);
    const int   rowVecLo = row * SqV;
    const int   baseVec  = rowVecLo + (chunkStart - HALO) / 4;

    #pragma unroll 1
    for (int it = 0; it < 9; it++) {                 // 9*128 covers 1152 vectors
        const int vecIdx = it * TPB + tid;
        const int gv     = baseVec + vecIdx;
        const int gvc    = min(max(gv, rowVecLo), rowVecLo + SqV - 1);
        int4 v = __ldg(tgt4 + gvc);
        const bool valid = (unsigned)(gv - rowVecLo) < (unsigned)SqV;

        unsigned nib = (v.x > 0 ? 1u : 0u) | (v.y > 0 ? 2u : 0u)
                     | (v.z > 0 ? 4u : 0u) | (v.w > 0 ? 8u : 0u);
        if (!valid) nib = 0;

        unsigned wv = nib << ((lane & 7) * 4);       // 8 lanes build one word
        wv |= __shfl_xor_sync(0xffffffffu, wv, 1);
        wv |= __shfl_xor_sync(0xffffffffu, wv, 2);
        wv |= __shfl_xor_sync(0xffffffffu, wv, 4);
        if ((lane & 7) == 0) sPos[GUARD + (vecIdx >> 3)] = wv;

        const unsigned ci = (unsigned)(vecIdx - HALO / 4);
        if (ci < (unsigned)(CHUNK / 4))
            sClsW[ci] = (unsigned)(v.x & 3) | ((unsigned)(v.y & 3) << 8)
                      | ((unsigned)(v.z & 3) << 16) | ((unsigned)(v.w & 3) << 24);
    }
    __syncthreads();

    // ---- Closed-form +-100 window mask per word (WIN=100 > 3*32).
    int cm0 = 0, hp0 = 0;
    {
        const unsigned* P = sPos + GUARD;
        #pragma unroll 1
        for (int k = tid; k < EXTW; k += TPB) {
            unsigned any5 = P[k-2] | P[k-1] | P[k] | P[k+1] | P[k+2];
            unsigned F    = any5 ? 0xffffffffu : 0u;

            unsigned u3 = P[k+3];                    // covers bits i >= b-4
            u3 |= u3 << 1;  u3 |= u3 << 2;  u3 |= u3 << 4;
            u3 |= u3 << 8;  u3 |= u3 << 16; u3 |= u3 >> 4;

            unsigned d3 = P[k-3];                    // covers bits i <= b+4
            d3 |= d3 >> 1;  d3 |= d3 >> 2;  d3 |= d3 >> 4;
            d3 |= d3 >> 8;  d3 |= d3 >> 16; d3 |= d3 << 4;

            unsigned n4 = P[k+4] & 0xFu;             // covers bits i >= b+28
            n4 |= n4 << 1; n4 |= n4 << 2;
            unsigned r4 = n4 << 28;

            unsigned h4 = P[k-4] >> 28;              // covers bits i <= b-28
            h4 |= h4 >> 1; h4 |= h4 >> 2;

            unsigned M = F | u3 | d3 | r4 | h4;
            sMsk[GUARD + k] = M;
            if ((unsigned)(k - HALO / 32) < (unsigned)(CHUNK / 32)) {
                cm0 += __popc(M);
                hp0 |= (P[k] != 0u);
            }
        }
    }
    __syncthreads();
    const unsigned* MW = sMsk + GUARD + HALO / 32;

    // ---- Main compute: 4 elements/group, 3x LDG.128, spill-free (R8 structure).
    const float LN2 = 0.69314718055994531f;
    const float a0 = __ldg(alpha + 0) * LN2, a1 = __ldg(alpha + 1) * LN2,
                a2 = __ldg(alpha + 2) * LN2;
    const float4* in4 = reinterpret_cast<const float4*>(
        inputs + ((size_t)row * Sq + (size_t)chunkStart) * 3);

    float sm = 0.f, sa = 0.f;

    #pragma unroll 1
    for (int k = 0; k < GRP; k++) {
        const int g = k * TPB + tid;                 // elements [4g, 4g+4)
        const unsigned tv = sClsW[g];
        const unsigned mk = MW[g >> 3] >> ((g & 7) * 4);
        float4 A = __ldcs(in4 + 3 * g + 0);
        float4 B = __ldcs(in4 + 3 * g + 1);
        float4 C = __ldcs(in4 + 3 * g + 2);

        elem(A.x, A.y, A.z, (int)( tv        & 3u), mk        & 1u, a0, a1, a2, sa, sm);
        elem(A.w, B.x, B.y, (int)((tv >>  8) & 3u), (mk >> 1) & 1u, a0, a1, a2, sa, sm);
        elem(B.z, B.w, C.x, (int)((tv >> 16) & 3u), (mk >> 2) & 1u, a0, a1, a2, sa, sm);
        elem(C.y, C.z, C.w, (int)((tv >> 24) & 3u), (mk >> 3) & 1u, a0, a1, a2, sa, sm);
    }

    // ---- Deterministic block reduction, one float4 store per block.
    int cm = cm0, hp = hp0;
    #pragma unroll
    for (int o = 16; o > 0; o >>= 1) {
        sm += __shfl_down_sync(0xffffffffu, sm, o);
        sa += __shfl_down_sync(0xffffffffu, sa, o);
        cm += __shfl_down_sync(0xffffffffu, cm, o);
        hp |= __shfl_down_sync(0xffffffffu, hp, o);
    }
    if (lane == 0) { rA[warp] = sm; rB[warp] = sa; rC[warp] = (float)cm; rH[warp] = hp; }
    __syncthreads();
    if (tid == 0) {
        float Am = 0.f, Bs = 0.f, Cc = 0.f; int H = 0;
        #pragma unroll
        for (int w = 0; w < NWARP; w++) { Am += rA[w]; Bs += rB[w]; Cc += rC[w]; H |= rH[w]; }
        g_part[row * CPR + chunk] = make_float4(Am, Bs, Cc, (float)H);
        __threadfence();
        unsigned old = atomicAdd(&g_done, 1u);
        sLast = (old == NBLK - 1);
    }
    __syncthreads();

    // ---- Last block finalizes (result independent of which block runs this).
    if (sLast) {
        __threadfence();
        if (tid < Bq) {
            float psm = 0.f, psa = 0.f, pcm = 0.f; int php = 0;
            #pragma unroll 4
            for (int k = 0; k < CPR; k++) {
                float4 p = __ldcg(&g_part[tid * CPR + k]);
                psm += p.x; psa += p.y; pcm += p.z; php |= (p.w != 0.f);
            }
            sRS[tid] = php ? psm : psa;
            sRC[tid] = php ? pcm : (float)Sq;
        }
        __syncthreads();
        if (tid == 0) {
            float ts = 0.f, tc = 0.f;
            #pragma unroll
            for (int i = 0; i < Bq; i++) { ts += sRS[i]; tc += sRC[i]; }
            out[0] = ts / tc;
            g_done = 0;   // reset for next graph replay
        }
    }
}

extern "C" void kernel_launch(void* const* d_in, const int* in_sizes, int n_in,
                              void* d_out, int out_size)
{
    const float* inputs  = (const float*)d_in[0];
    const int*   targets = (const int*)d_in[1];
    const float* alpha   = (const float*)d_in[2];

    dim3 grid(CPR, Bq);
    focal_main<<<grid, TPB>>>(inputs, targets, alpha, (float*)d_out);
}